// round 1
// baseline (speedup 1.0000x reference)
#include <cuda_runtime.h>
#include <math.h>

typedef unsigned long long u64;

#define BATCH 512
#define TLEN  1024
#define HID   64
#define M_TOTAL (BATCH*TLEN)   // 524288 rows

// Scratch: pre-activations + ping/pong hidden-state buffers (134 MB each).
__device__ __align__(16) float g_pre[M_TOTAL*HID];
__device__ __align__(16) float g_h1 [M_TOTAL*HID];
__device__ __align__(16) float g_h2 [M_TOTAL*HID];

// ---- packed fp32x2 helpers (sm_100+ packed-FMA path, 2x fp32 FMA throughput) ----
__device__ __forceinline__ u64 pk2(float x, float y) {
    u64 r; asm("mov.b64 %0,{%1,%2};" : "=l"(r) : "f"(x), "f"(y)); return r;
}
__device__ __forceinline__ void upk2(u64 v, float &x, float &y) {
    asm("mov.b64 {%0,%1},%2;" : "=f"(x), "=f"(y) : "l"(v));
}
#define FMA2(d,a,b,c) asm("fma.rn.f32x2 %0,%1,%2,%3;" : "=l"(d) : "l"(a), "l"(b), "l"(c))
#define ADD2(d,a,b)   asm("add.rn.f32x2 %0,%1,%2;"    : "=l"(d) : "l"(a), "l"(b))

// ============================================================================
// GEMM: Out[m, n] = sum_k X[m,k] * W[n,k] + b1[n] (+ b2[n]), N = 64, K <= 64.
// TM = 32 rows per block, 128 threads. X staged in smem duplicated {x,x};
// W staged as n-pairs {W[2p][k], W[2p+1][k]}. Inner loop per k:
//   4x LDS.64 (broadcast-ish) + 1x LDS.128 + 8x FFMA2  -> FMA-pipe bound.
// ============================================================================
__global__ void __launch_bounds__(128) gemm64(
    const float* __restrict__ Xext, int xsel,
    const float* __restrict__ W,
    const float* __restrict__ b1, const float* __restrict__ b2,
    float* __restrict__ Oext, int osel, int K)
{
    const float* X = (xsel == 0) ? Xext : (xsel == 1 ? g_h1 : g_h2);
    float* Out     = (osel == 0) ? Oext : g_pre;

    __shared__ __align__(16) u64 Xs2[32*64];   // 16 KB: {x,x} pairs, [m][k]
    __shared__ __align__(16) u64 Wp [64*32];   // 16 KB: Wp[k*32+p] = {W[2p][k], W[2p+1][k]}

    const int tid = threadIdx.x;
    const long m0 = (long)blockIdx.x * 32;

    // Stage X tile (zero-pad k >= K). Consecutive tid -> consecutive k: coalesced.
    #pragma unroll
    for (int i = 0; i < 16; i++) {
        int idx = tid + i*128;              // 0..2047
        int m = idx >> 6, k = idx & 63;
        float v = (k < K) ? X[(m0 + m)*K + k] : 0.f;
        Xs2[idx] = pk2(v, v);
    }
    // Stage W as n-pairs (L1/L2-hot after first wave; tiny).
    #pragma unroll
    for (int i = 0; i < 16; i++) {
        int idx = tid + i*128;              // 0..2047
        int k = idx >> 5, np = idx & 31;
        int n = np * 2;
        float w0 = 0.f, w1 = 0.f;
        if (k < K) { w0 = __ldg(&W[n*K + k]); w1 = __ldg(&W[(n+1)*K + k]); }
        Wp[idx] = pk2(w0, w1);
    }
    __syncthreads();

    const int nt = tid & 15;                // 16 n-groups of 4 columns
    const int mt = tid >> 4;                // 8 m-groups of 4 rows
    const int n0 = nt * 4;
    const int mr = mt * 4;

    // Bias init (b2 optional).
    float bb0 = b1[n0+0], bb1 = b1[n0+1], bb2 = b1[n0+2], bb3 = b1[n0+3];
    if (b2) { bb0 += b2[n0+0]; bb1 += b2[n0+1]; bb2 += b2[n0+2]; bb3 += b2[n0+3]; }

    u64 acc[4][2];
    #pragma unroll
    for (int i = 0; i < 4; i++) { acc[i][0] = pk2(bb0, bb1); acc[i][1] = pk2(bb2, bb3); }

    #pragma unroll
    for (int k = 0; k < 64; k++) {
        ulonglong2 w = *reinterpret_cast<const ulonglong2*>(&Wp[k*32 + nt*2]); // LDS.128
        #pragma unroll
        for (int i = 0; i < 4; i++) {
            u64 a = Xs2[(mr + i)*64 + k];   // LDS.64, {x,x}
            FMA2(acc[i][0], a, w.x, acc[i][0]);
            FMA2(acc[i][1], a, w.y, acc[i][1]);
        }
    }

    #pragma unroll
    for (int i = 0; i < 4; i++) {
        float f0, f1, f2, f3;
        upk2(acc[i][0], f0, f1);
        upk2(acc[i][1], f2, f3);
        *reinterpret_cast<float4*>(&Out[(m0 + mr + i)*64 + n0]) = make_float4(f0, f1, f2, f3);
    }
}

// ============================================================================
// Recurrent scan: h_t = tanh(pre_t + h_{t-1} @ Wh^T), over T = 1024 steps.
// 128 blocks x 128 threads: 4 batch rows/block, 32 threads/row, each thread
// owns output pair {j, j+1}. Wh^T column pairs live in REGISTERS (64 x f32x2);
// h lives in shared, PRE-DUPLICATED as {h,h} so the k-loop is
// 1 broadcast LDS.64 + 1 FFMA2 per k, no pack instructions.
// pre is prefetched 4 steps ahead to hide DRAM latency.
// ============================================================================
__global__ void __launch_bounds__(128) rnn_scan(const float* __restrict__ Whh, int osel)
{
    float* Out = (osel == 1) ? g_h1 : g_h2;

    __shared__ __align__(16) u64 hs[2][4][64];   // double-buffered {h,h} pairs, 4 KB

    const int tid = threadIdx.x;
    #pragma unroll
    for (int i = 0; i < 4; i++) ((u64*)hs)[tid + i*128] = 0ull;   // h0 = 0 (both buffers)
    __syncthreads();

    const int r  = tid >> 5;        // row within block (warp id)
    const int jt = tid & 31;        // pair index
    const int j  = jt * 2;
    const int b  = blockIdx.x * 4 + r;

    // Weight column pair for outputs j, j+1:  w2[k] = {Wh[j][k], Wh[j+1][k]}
    u64 w2[64];
    #pragma unroll
    for (int k = 0; k < 64; k++)
        w2[k] = pk2(__ldg(&Whh[j*64 + k]), __ldg(&Whh[(j+1)*64 + k]));

    const u64* prow = reinterpret_cast<const u64*>(g_pre) + (long)b * TLEN * 32 + jt;
    u64*       orow = reinterpret_cast<u64*>(Out)        + (long)b * TLEN * 32 + jt;

    // 4-deep prefetch ring for pre.
    u64 pb[4];
    #pragma unroll
    for (int q = 0; q < 4; q++) pb[q] = __ldg(&prow[q * 32]);

    int p = 0;
    #pragma unroll 4
    for (int t = 0; t < TLEN; t++) {
        u64 cur = pb[t & 3];
        if (t + 4 < TLEN) pb[t & 3] = __ldg(&prow[(long)(t + 4) * 32]);

        u64 a0 = cur, a1 = 0ull, a2 = 0ull, a3 = 0ull;   // 0ull == {0.f, 0.f}
        const u64* hrow = hs[p][r];
        #pragma unroll
        for (int k = 0; k < 64; k += 4) {
            FMA2(a0, hrow[k+0], w2[k+0], a0);
            FMA2(a1, hrow[k+1], w2[k+1], a1);
            FMA2(a2, hrow[k+2], w2[k+2], a2);
            FMA2(a3, hrow[k+3], w2[k+3], a3);
        }
        ADD2(a0, a0, a1); ADD2(a2, a2, a3); ADD2(a0, a0, a2);

        float x0, x1; upk2(a0, x0, x1);
        float h0 = tanhf(x0);
        float h1 = tanhf(x1);

        orow[(long)t * 32] = pk2(h0, h1);                 // STG.64, coalesced
        ulonglong2 hh; hh.x = pk2(h0, h0); hh.y = pk2(h1, h1);
        *reinterpret_cast<ulonglong2*>(&hs[p ^ 1][r][j]) = hh;  // STS.128

        __syncthreads();
        p ^= 1;
    }
}

// ============================================================================
// Launch: 4 x (input-GEMM -> scan) + final FC GEMM. All default-stream,
// kernel launches only -> graph-capturable, allocation-free.
// ============================================================================
extern "C" void kernel_launch(void* const* d_in, const int* in_sizes, int n_in,
                              void* d_out, int out_size)
{
    const float* x    = (const float*)d_in[0];   // [512,1024,52]
    const float* Wih0 = (const float*)d_in[1];   // [64,52]
    const float* Whh0 = (const float*)d_in[2];   // [64,64]
    const float* bih0 = (const float*)d_in[3];   // [64]
    const float* bhh0 = (const float*)d_in[4];   // [64]
    const float* Wih  = (const float*)d_in[5];   // [3,64,64]
    const float* Whh  = (const float*)d_in[6];   // [3,64,64]
    const float* bih  = (const float*)d_in[7];   // [3,64]
    const float* bhh  = (const float*)d_in[8];   // [3,64]
    const float* Wfc  = (const float*)d_in[9];   // [64,64]
    const float* bfc  = (const float*)d_in[10];  // [64]
    float* out = (float*)d_out;

    const int GB = M_TOTAL / 32;   // 16384 GEMM blocks

    // Layer 0: x -> g_h1
    gemm64<<<GB, 128>>>(x, 0, Wih0, bih0, bhh0, nullptr, 3, 52);
    rnn_scan<<<128, 128>>>(Whh0, 1);

    // Layers 1..3: g_h1 -> g_h2 -> g_h1 -> g_h2
    const int insel[3]  = {1, 2, 1};
    const int outsel[3] = {2, 1, 2};
    for (int l = 0; l < 3; l++) {
        gemm64<<<GB, 128>>>(nullptr, insel[l], Wih + l*4096, bih + l*64, bhh + l*64,
                            nullptr, 3, 64);
        rnn_scan<<<128, 128>>>(Whh + l*4096, outsel[l]);
    }

    // Final FC: g_h2 -> d_out
    gemm64<<<GB, 128>>>(nullptr, 2, Wfc, bfc, nullptr, out, 0, 64);
}

// round 2
// speedup vs baseline: 1.1591x; 1.1591x over previous
#include <cuda_runtime.h>
#include <math.h>

typedef unsigned long long u64;

#define BATCH 512
#define TLEN  1024
#define HID   64
#define M_TOTAL (BATCH*TLEN)   // 524288 rows

// Scratch: pre-activations + ping/pong hidden-state buffers (134 MB each).
__device__ __align__(16) float g_pre[M_TOTAL*HID];
__device__ __align__(16) float g_h1 [M_TOTAL*HID];
__device__ __align__(16) float g_h2 [M_TOTAL*HID];

// ---- packed fp32x2 helpers ----
__device__ __forceinline__ u64 pk2(float x, float y) {
    u64 r; asm("mov.b64 %0,{%1,%2};" : "=l"(r) : "f"(x), "f"(y)); return r;
}
__device__ __forceinline__ void upk2(u64 v, float &x, float &y) {
    asm("mov.b64 {%0,%1},%2;" : "=f"(x), "=f"(y) : "l"(v));
}
#define FMA2(d,a,b,c) asm("fma.rn.f32x2 %0,%1,%2,%3;" : "=l"(d) : "l"(a), "l"(b), "l"(c))
#define ADD2(d,a,b)   asm("add.rn.f32x2 %0,%1,%2;"    : "=l"(d) : "l"(a), "l"(b))

// Fast tanh: tanh(x) = (e^{2x}-1)/(e^{2x}+1) via MUFU.EX2 + MUFU.RCP.
// ex2.approx / rcp.approx rel err ~2^-22 -> ~1e-6 total, far under 1e-3 tol.
__device__ __forceinline__ float tanh_fast(float x) {
    float xc = fminf(fmaxf(x, -15.0f), 15.0f);
    float e;
    asm("ex2.approx.f32 %0, %1;" : "=f"(e) : "f"(xc * 2.885390081777927f)); // 2*log2(e)
    float r;
    asm("rcp.approx.f32 %0, %1;" : "=f"(r) : "f"(e + 1.0f));
    return (e - 1.0f) * r;
}

// ============================================================================
// GEMM: Out[m,n] = sum_k X[m,k]*W[n,k] + b1[n] (+b2[n]).  N=64, K<=64.
// Block: 128 threads, tile 128 rows x 64 cols; thread: 8 rows x 8 cols.
// Per k per thread: 8 LDS.64 (x dup, swizzled conflict-free) + 2 LDS.128 (w
// pairs) + 32 FFMA2  ->  FMA-pipe bound (4096 cyc/block floor).
// K staged in two 32-wide halves to stay within 48KB static smem.
// ============================================================================
__global__ void __launch_bounds__(128) gemm64(
    const float* __restrict__ Xext, int xsel,
    const float* __restrict__ W,
    const float* __restrict__ b1, const float* __restrict__ b2,
    float* __restrict__ Oext, int osel, int K)
{
    const float* X = (xsel == 0) ? Xext : (xsel == 1 ? g_h1 : g_h2);
    float* Out     = (osel == 0) ? Oext : g_pre;

    __shared__ __align__(16) u64 Xd[128*32];  // [m][kk'] {x,x} dup, swizzled, 32KB
    __shared__ __align__(16) u64 Wp[32*32];   // [kk][np'] {W[2np][k],W[2np+1][k]}, 8KB

    const int tid = threadIdx.x;
    const long m0 = (long)blockIdx.x * 128;

    const int nt  = tid & 7;     // 8 col-groups (8 cols each)
    const int mt  = tid >> 3;    // 16 row-groups (8 rows each)
    const int np0 = nt * 4;      // first n-pair of this thread
    const int mr  = mt * 8;      // first row of this thread
    const int xsw = (mt & 3) << 2;  // x swizzle (constant per thread)

    // bias (b2 optional)
    u64 acc[8][4];
    {
        u64 bias[4];
        #pragma unroll
        for (int p = 0; p < 4; p++) {
            int n = (np0 + p) * 2;
            float v0 = b1[n], v1 = b1[n+1];
            if (b2) { v0 += b2[n]; v1 += b2[n+1]; }
            bias[p] = pk2(v0, v1);
        }
        #pragma unroll
        for (int i = 0; i < 8; i++)
            #pragma unroll
            for (int p = 0; p < 4; p++) acc[i][p] = bias[p];
    }

    #pragma unroll
    for (int kh = 0; kh < 2; kh++) {
        const int kbase = kh * 32;
        __syncthreads();   // protect smem reuse across halves

        // ---- stage X half: 128 rows x 32 k, coalesced reads, swizzled dup store
        #pragma unroll 8
        for (int i = 0; i < 32; i++) {
            int idx = i * 128 + tid;       // 0..4095
            int m  = idx >> 5;
            int kk = idx & 31;
            int k  = kbase + kk;
            float v = (k < K) ? X[(m0 + m) * (long)K + k] : 0.f;
            Xd[m * 32 + (kk ^ (((m >> 3) & 3) << 2))] = pk2(v, v);
        }
        // ---- stage W half: 32 n-pairs x 32 k, coalesced reads, swizzled store
        #pragma unroll
        for (int i = 0; i < 8; i++) {
            int idx = i * 128 + tid;       // 0..1023
            int np = idx >> 5;
            int kk = idx & 31;
            int k  = kbase + kk;
            float w0 = 0.f, w1 = 0.f;
            if (k < K) {
                w0 = W[(2*np)   * (long)K + k];
                w1 = W[(2*np+1) * (long)K + k];
            }
            Wp[kk * 32 + (np ^ ((kk & 7) << 2))] = pk2(w0, w1);
        }
        __syncthreads();

        // ---- compute half
        #pragma unroll 8
        for (int kk = 0; kk < 32; kk++) {
            int wbase = kk * 32 + (np0 ^ ((kk & 7) << 2));
            ulonglong2 wA = *reinterpret_cast<const ulonglong2*>(&Wp[wbase]);
            ulonglong2 wB = *reinterpret_cast<const ulonglong2*>(&Wp[wbase + 2]);
            const u64* xcol = &Xd[mr * 32 + (kk ^ xsw)];
            #pragma unroll
            for (int i = 0; i < 8; i++) {
                u64 xv = xcol[i * 32];
                FMA2(acc[i][0], xv, wA.x, acc[i][0]);
                FMA2(acc[i][1], xv, wA.y, acc[i][1]);
                FMA2(acc[i][2], xv, wB.x, acc[i][2]);
                FMA2(acc[i][3], xv, wB.y, acc[i][3]);
            }
        }
    }

    // ---- write out: 8 rows x 8 cols per thread, 2x STG.128 per row
    const int n0 = np0 * 2;
    #pragma unroll
    for (int i = 0; i < 8; i++) {
        float* dst = &Out[(m0 + mr + i) * 64 + n0];
        ulonglong2 v0, v1;
        v0.x = acc[i][0]; v0.y = acc[i][1];
        v1.x = acc[i][2]; v1.y = acc[i][3];
        *reinterpret_cast<ulonglong2*>(dst)     = v0;
        *reinterpret_cast<ulonglong2*>(dst + 4) = v1;
    }
}

// ============================================================================
// Recurrent scan: h_t = tanh(pre_t + h_{t-1} @ Wh^T), T=1024 steps.
// One batch row per WARP (512 blocks x 32 threads) -> no block barrier, only
// __syncwarp per step. Wh column pairs in registers (64 u64). h kept in smem
// pre-duplicated {h,h}; read as 8x broadcast LDS.128 per step. Fast tanh.
// Per-step floor: 64 FFMA2 (128 FMA-pipe cyc) + ~50 cyc exposed latency.
// ============================================================================
__global__ void __launch_bounds__(32) rnn_scan(const float* __restrict__ Whh, int osel)
{
    float* Out = (osel == 1) ? g_h1 : g_h2;

    __shared__ __align__(16) u64 hs[2][64];   // double-buffered {h,h} pairs

    const int jt = threadIdx.x;     // pair index 0..31
    const int j  = jt * 2;
    const int b  = blockIdx.x;      // batch row

    #pragma unroll
    for (int i = 0; i < 4; i++) ((u64*)hs)[jt + i*32] = 0ull;
    __syncwarp();

    // weight column pair for outputs j, j+1
    u64 w2[64];
    #pragma unroll
    for (int k = 0; k < 64; k++)
        w2[k] = pk2(__ldg(&Whh[j*64 + k]), __ldg(&Whh[(j+1)*64 + k]));

    const u64* prow = reinterpret_cast<const u64*>(g_pre) + (long)b * TLEN * 32 + jt;
    u64*       orow = reinterpret_cast<u64*>(Out)        + (long)b * TLEN * 32 + jt;

    // 4-deep prefetch ring for pre (covers ~700+ cyc DRAM latency)
    u64 pb[4];
    #pragma unroll
    for (int q = 0; q < 4; q++) pb[q] = __ldg(&prow[q * 32]);

    int p = 0;
    for (int t = 0; t < TLEN; t++) {
        u64 cur = pb[t & 3];
        if (t + 4 < TLEN) pb[t & 3] = __ldg(&prow[(long)(t + 4) * 32]);

        u64 a0 = cur, a1 = 0ull, a2 = 0ull, a3 = 0ull;
        const u64* hrow = hs[p];
        #pragma unroll
        for (int k = 0; k < 64; k += 4) {
            ulonglong2 hA = *reinterpret_cast<const ulonglong2*>(&hrow[k]);
            ulonglong2 hB = *reinterpret_cast<const ulonglong2*>(&hrow[k+2]);
            FMA2(a0, hA.x, w2[k+0], a0);
            FMA2(a1, hA.y, w2[k+1], a1);
            FMA2(a2, hB.x, w2[k+2], a2);
            FMA2(a3, hB.y, w2[k+3], a3);
        }
        ADD2(a0, a0, a1); ADD2(a2, a2, a3); ADD2(a0, a0, a2);

        float x0, x1; upk2(a0, x0, x1);
        float h0 = tanh_fast(x0);
        float h1 = tanh_fast(x1);

        orow[(long)t * 32] = pk2(h0, h1);            // STG.64, coalesced per warp
        ulonglong2 hh; hh.x = pk2(h0, h0); hh.y = pk2(h1, h1);
        *reinterpret_cast<ulonglong2*>(&hs[p ^ 1][j]) = hh;   // STS.128

        __syncwarp();
        p ^= 1;
    }
}

// ============================================================================
// Launch: 4 x (input-GEMM -> scan) + final FC GEMM. Single stream, kernel
// launches only -> graph-capturable, allocation-free.
// ============================================================================
extern "C" void kernel_launch(void* const* d_in, const int* in_sizes, int n_in,
                              void* d_out, int out_size)
{
    const float* x    = (const float*)d_in[0];   // [512,1024,52]
    const float* Wih0 = (const float*)d_in[1];   // [64,52]
    const float* Whh0 = (const float*)d_in[2];   // [64,64]
    const float* bih0 = (const float*)d_in[3];   // [64]
    const float* bhh0 = (const float*)d_in[4];   // [64]
    const float* Wih  = (const float*)d_in[5];   // [3,64,64]
    const float* Whh  = (const float*)d_in[6];   // [3,64,64]
    const float* bih  = (const float*)d_in[7];   // [3,64]
    const float* bhh  = (const float*)d_in[8];   // [3,64]
    const float* Wfc  = (const float*)d_in[9];   // [64,64]
    const float* bfc  = (const float*)d_in[10];  // [64]
    float* out = (float*)d_out;

    const int GB = M_TOTAL / 128;   // 4096 GEMM blocks

    // Layer 0: x -> pre -> g_h1
    gemm64<<<GB, 128>>>(x, 0, Wih0, bih0, bhh0, nullptr, 3, 52);
    rnn_scan<<<BATCH, 32>>>(Whh0, 1);

    // Layers 1..3: g_h1 -> g_h2 -> g_h1 -> g_h2
    const int insel[3]  = {1, 2, 1};
    const int outsel[3] = {2, 1, 2};
    for (int l = 0; l < 3; l++) {
        gemm64<<<GB, 128>>>(nullptr, insel[l], Wih + l*4096, bih + l*64, bhh + l*64,
                            nullptr, 3, 64);
        rnn_scan<<<BATCH, 32>>>(Whh + l*4096, outsel[l]);
    }

    // Final FC: g_h2 -> d_out
    gemm64<<<GB, 128>>>(nullptr, 2, Wfc, bfc, nullptr, out, 0, 64);
}

// round 3
// speedup vs baseline: 1.8202x; 1.5703x over previous
#include <cuda_runtime.h>
#include <math.h>

typedef unsigned long long u64;

#define BATCH 512
#define TLEN  1024
#define HID   64
#define M_TOTAL (BATCH*TLEN)   // 524288 rows

// Scratch: pre-activations + ping/pong hidden-state buffers (134 MB each).
__device__ __align__(16) float g_pre[M_TOTAL*HID];
__device__ __align__(16) float g_h1 [M_TOTAL*HID];
__device__ __align__(16) float g_h2 [M_TOTAL*HID];

// ---- packed fp32x2 helpers ----
__device__ __forceinline__ u64 pk2(float x, float y) {
    u64 r; asm("mov.b64 %0,{%1,%2};" : "=l"(r) : "f"(x), "f"(y)); return r;
}
__device__ __forceinline__ void upk2(u64 v, float &x, float &y) {
    asm("mov.b64 {%0,%1},%2;" : "=f"(x), "=f"(y) : "l"(v));
}
#define FMA2(d,a,b,c) asm("fma.rn.f32x2 %0,%1,%2,%3;" : "=l"(d) : "l"(a), "l"(b), "l"(c))
#define ADD2(d,a,b)   asm("add.rn.f32x2 %0,%1,%2;"    : "=l"(d) : "l"(a), "l"(b))

// Fast tanh: tanh(x) = (e^{2x}-1)/(e^{2x}+1) via MUFU.EX2 + MUFU.RCP.
// rel err ~1e-6, far under the 1e-3 tolerance.
__device__ __forceinline__ float tanh_fast(float x) {
    float xc = fminf(fmaxf(x, -15.0f), 15.0f);
    float e;
    asm("ex2.approx.f32 %0, %1;" : "=f"(e) : "f"(xc * 2.885390081777927f)); // 2*log2(e)
    float r;
    asm("rcp.approx.f32 %0, %1;" : "=f"(r) : "f"(e + 1.0f));
    return (e - 1.0f) * r;
}

// ============================================================================
// GEMM: Out[m,n] = sum_k X[m,k]*W[n,k] + b1[n] (+b2[n]).  N=64, K<=64.
// Block: 128 threads, tile 128 rows x 64 cols; thread: 8 rows x 8 cols.
// (unchanged from R2: ~148us/launch, FMA-bound enough; scans dominate)
// ============================================================================
__global__ void __launch_bounds__(128) gemm64(
    const float* __restrict__ Xext, int xsel,
    const float* __restrict__ W,
    const float* __restrict__ b1, const float* __restrict__ b2,
    float* __restrict__ Oext, int osel, int K)
{
    const float* X = (xsel == 0) ? Xext : (xsel == 1 ? g_h1 : g_h2);
    float* Out     = (osel == 0) ? Oext : g_pre;

    __shared__ __align__(16) u64 Xd[128*32];  // {x,x} dup, swizzled, 32KB
    __shared__ __align__(16) u64 Wp[32*32];   // {W[2np][k],W[2np+1][k]}, 8KB

    const int tid = threadIdx.x;
    const long m0 = (long)blockIdx.x * 128;

    const int nt  = tid & 7;
    const int mt  = tid >> 3;
    const int np0 = nt * 4;
    const int mr  = mt * 8;
    const int xsw = (mt & 3) << 2;

    u64 acc[8][4];
    {
        u64 bias[4];
        #pragma unroll
        for (int p = 0; p < 4; p++) {
            int n = (np0 + p) * 2;
            float v0 = b1[n], v1 = b1[n+1];
            if (b2) { v0 += b2[n]; v1 += b2[n+1]; }
            bias[p] = pk2(v0, v1);
        }
        #pragma unroll
        for (int i = 0; i < 8; i++)
            #pragma unroll
            for (int p = 0; p < 4; p++) acc[i][p] = bias[p];
    }

    #pragma unroll
    for (int kh = 0; kh < 2; kh++) {
        const int kbase = kh * 32;
        __syncthreads();

        #pragma unroll 8
        for (int i = 0; i < 32; i++) {
            int idx = i * 128 + tid;
            int m  = idx >> 5;
            int kk = idx & 31;
            int k  = kbase + kk;
            float v = (k < K) ? X[(m0 + m) * (long)K + k] : 0.f;
            Xd[m * 32 + (kk ^ (((m >> 3) & 3) << 2))] = pk2(v, v);
        }
        #pragma unroll
        for (int i = 0; i < 8; i++) {
            int idx = i * 128 + tid;
            int np = idx >> 5;
            int kk = idx & 31;
            int k  = kbase + kk;
            float w0 = 0.f, w1 = 0.f;
            if (k < K) {
                w0 = W[(2*np)   * (long)K + k];
                w1 = W[(2*np+1) * (long)K + k];
            }
            Wp[kk * 32 + (np ^ ((kk & 7) << 2))] = pk2(w0, w1);
        }
        __syncthreads();

        #pragma unroll 8
        for (int kk = 0; kk < 32; kk++) {
            int wbase = kk * 32 + (np0 ^ ((kk & 7) << 2));
            ulonglong2 wA = *reinterpret_cast<const ulonglong2*>(&Wp[wbase]);
            ulonglong2 wB = *reinterpret_cast<const ulonglong2*>(&Wp[wbase + 2]);
            const u64* xcol = &Xd[mr * 32 + (kk ^ xsw)];
            #pragma unroll
            for (int i = 0; i < 8; i++) {
                u64 xv = xcol[i * 32];
                FMA2(acc[i][0], xv, wA.x, acc[i][0]);
                FMA2(acc[i][1], xv, wA.y, acc[i][1]);
                FMA2(acc[i][2], xv, wB.x, acc[i][2]);
                FMA2(acc[i][3], xv, wB.y, acc[i][3]);
            }
        }
    }

    const int n0 = np0 * 2;
    #pragma unroll
    for (int i = 0; i < 8; i++) {
        float* dst = &Out[(m0 + mr + i) * 64 + n0];
        ulonglong2 v0, v1;
        v0.x = acc[i][0]; v0.y = acc[i][1];
        v1.x = acc[i][2]; v1.y = acc[i][3];
        *reinterpret_cast<ulonglong2*>(dst)     = v0;
        *reinterpret_cast<ulonglong2*>(dst + 4) = v1;
    }
}

// ============================================================================
// Recurrent scan: h_t = tanh(pre_t + h_{t-1} @ Wh^T), T=1024 steps.
// One batch row per 64-thread block; each thread owns ONE output j, with the
// K dimension packed in f32x2 pairs:
//   w2[kk] = {Wh[j][2kk], Wh[j][2kk+1]}  -> 32 u64 = 64 regs (fits, no spill)
//   h is plain f32[64] in smem; packed-k layout means LDS.128 broadcast reads
//   deliver exactly the needed {h[2kk],h[2kk+1]} pairs, no duplication.
// Per thread per step: 16 LDS.128 (broadcast) + 32 FFMA2 (4 chains of 8) +
// 1 tanh + STG.32 + STS.32 + BAR(nw=2).
// ============================================================================
__global__ void __launch_bounds__(64) rnn_scan(const float* __restrict__ Whh, int osel)
{
    float* Out = (osel == 1) ? g_h1 : g_h2;

    __shared__ __align__(16) float hsm[2][64];   // double-buffered h, 512B

    const int j = threadIdx.x;      // output index 0..63
    const int b = blockIdx.x;       // batch row

    hsm[0][j] = 0.f;
    hsm[1][j] = 0.f;
    __syncthreads();

    // Weight row j, packed along k: w2[kk] = {Wh[j][2kk], Wh[j][2kk+1]}
    u64 w2[32];
    {
        const float4* wr = reinterpret_cast<const float4*>(Whh + j * 64);
        #pragma unroll
        for (int q = 0; q < 16; q++) {
            float4 w = __ldg(&wr[q]);
            w2[2*q]   = pk2(w.x, w.y);
            w2[2*q+1] = pk2(w.z, w.w);
        }
    }

    const float* prow = g_pre + (long)b * TLEN * 64 + j;
    float*       orow = Out   + (long)b * TLEN * 64 + j;

    // 8-deep prefetch ring for pre (hides ~1000 cyc DRAM latency at ~170cyc/step)
    float pb[8];
    #pragma unroll
    for (int q = 0; q < 8; q++) pb[q] = __ldg(&prow[q * 64]);

    int p = 0;
    for (int t = 0; t < TLEN; t++) {
        float cur = pb[t & 7];
        if (t + 8 < TLEN) pb[t & 7] = __ldg(&prow[(long)(t + 8) * 64]);

        const ulonglong2* H = reinterpret_cast<const ulonglong2*>(hsm[p]);
        u64 a0 = 0ull, a1 = 0ull, a2 = 0ull, a3 = 0ull;
        #pragma unroll
        for (int q = 0; q < 4; q++) {
            ulonglong2 hA = H[4*q+0];   // pairs 8q+0, 8q+1  (broadcast LDS.128)
            ulonglong2 hB = H[4*q+1];
            ulonglong2 hC = H[4*q+2];
            ulonglong2 hD = H[4*q+3];
            FMA2(a0, hA.x, w2[8*q+0], a0);
            FMA2(a1, hA.y, w2[8*q+1], a1);
            FMA2(a2, hB.x, w2[8*q+2], a2);
            FMA2(a3, hB.y, w2[8*q+3], a3);
            FMA2(a0, hC.x, w2[8*q+4], a0);
            FMA2(a1, hC.y, w2[8*q+5], a1);
            FMA2(a2, hD.x, w2[8*q+6], a2);
            FMA2(a3, hD.y, w2[8*q+7], a3);
        }
        ADD2(a0, a0, a1); ADD2(a2, a2, a3); ADD2(a0, a0, a2);

        float lo, hi; upk2(a0, lo, hi);
        float h = tanh_fast(cur + lo + hi);

        orow[(long)t * 64] = h;     // STG.32, 256B/block coalesced
        hsm[p ^ 1][j] = h;          // STS.32
        __syncthreads();
        p ^= 1;
    }
}

// ============================================================================
// Launch: 4 x (input-GEMM -> scan) + final FC GEMM. Single stream, kernel
// launches only -> graph-capturable, allocation-free.
// ============================================================================
extern "C" void kernel_launch(void* const* d_in, const int* in_sizes, int n_in,
                              void* d_out, int out_size)
{
    const float* x    = (const float*)d_in[0];   // [512,1024,52]
    const float* Wih0 = (const float*)d_in[1];   // [64,52]
    const float* Whh0 = (const float*)d_in[2];   // [64,64]
    const float* bih0 = (const float*)d_in[3];   // [64]
    const float* bhh0 = (const float*)d_in[4];   // [64]
    const float* Wih  = (const float*)d_in[5];   // [3,64,64]
    const float* Whh  = (const float*)d_in[6];   // [3,64,64]
    const float* bih  = (const float*)d_in[7];   // [3,64]
    const float* bhh  = (const float*)d_in[8];   // [3,64]
    const float* Wfc  = (const float*)d_in[9];   // [64,64]
    const float* bfc  = (const float*)d_in[10];  // [64]
    float* out = (float*)d_out;

    const int GB = M_TOTAL / 128;   // 4096 GEMM blocks

    // Layer 0: x -> pre -> g_h1
    gemm64<<<GB, 128>>>(x, 0, Wih0, bih0, bhh0, nullptr, 3, 52);
    rnn_scan<<<BATCH, 64>>>(Whh0, 1);

    // Layers 1..3: g_h1 -> g_h2 -> g_h1 -> g_h2
    const int insel[3]  = {1, 2, 1};
    const int outsel[3] = {2, 1, 2};
    for (int l = 0; l < 3; l++) {
        gemm64<<<GB, 128>>>(nullptr, insel[l], Wih + l*4096, bih + l*64, bhh + l*64,
                            nullptr, 3, 64);
        rnn_scan<<<BATCH, 64>>>(Whh + l*4096, outsel[l]);
    }

    // Final FC: g_h2 -> d_out
    gemm64<<<GB, 128>>>(nullptr, 2, Wfc, bfc, nullptr, out, 0, 64);
}